// round 11
// baseline (speedup 1.0000x reference)
// AttentiveLinear as ONE symmetric-reduced GEMM [8192 x 8832] x [8832 x 128]:
//   y[n,o] = sum_{j<=i} x_j x_i Wfold[j,i,o] + sum_i x_i (Wb+bw)[i,o] + bb[o]
// R10: crossbar-ledger optimum. M-tile 64, 8 warps x (32x32) warp tiles
// (m=n=32 minimizes fragment wavefronts), grid 128 (halves L2 B-traffic).
// B in fragment order (cp.async lands ready), 3-stage ring, tf32 HMMA.
#include <cuda_runtime.h>
#include <cstdint>
#include <cstddef>

static constexpr int NK = 8832;        // 8704 pair rows (j-grouped, 8-padded) + 128 bias rows
static constexpr int PAIRS = 8704;
static constexpr int NKB = 276;        // NK / 32
static constexpr int NCHUNK = 1104;    // NK / 8

// g_Ws in per-kb fragment order:
//  [kb][ks(4)][wn(4)][hb(2: b0/b1)][lane(32)=(gid*4+tg)][nt(4)]  (4096 floats/kb)
__device__ __align__(16) float g_Ws[NK * 128];
__device__ uint32_t g_cidx[NCHUNK];    // (j<<16)|(i0<<8); j==255 -> bias rows

__device__ __forceinline__ float tf32_rna(float v) {
    uint32_t u;
    asm("cvt.rna.tf32.f32 %0, %1;" : "=r"(u) : "f"(v));
    return __uint_as_float(u);
}
__device__ __forceinline__ uint32_t smem_u32(const void* p) {
    uint32_t a;
    asm("{ .reg .u64 t; cvta.to.shared.u64 t, %1; cvt.u32.u64 %0, t; }" : "=r"(a) : "l"(p));
    return a;
}

// ---------------- prep kernel (unchanged layout from R8/R9) ----------------
__global__ void k_prepW(const float* __restrict__ Ww, const float* __restrict__ Wb,
                        const float* __restrict__ bw) {
    __shared__ int sj, se;
    const int t = blockIdx.x, o = threadIdx.x;
    if (threadIdx.x == 0) {
        int j = 0, e = 0;
        if (t < PAIRS) {
            int s = 0;
            for (j = 0; j < 128; j++) {
                int pj = ((128 - j) + 7) & ~7;
                if (t < s + pj) break;
                s += pj;
            }
            e = t - s;
        } else {
            j = 255; e = t - PAIRS;     // bias rows, i = e
        }
        sj = j; se = e;
        if ((t & 7) == 0) {
            int i0 = (j == 255) ? e : (j + e < 128 ? j + e : 127);
            g_cidx[t >> 3] = ((uint32_t)j << 16) | ((uint32_t)i0 << 8);
        }
    }
    __syncthreads();
    const int j = sj, e = se;
    float v = 0.0f;
    if (j == 255) {
        v = Wb[e * 128 + o] + bw[e * 128 + o];
    } else if (e < 128 - j) {
        const int i = j + e;
        if (e == 0) v = Ww[(size_t)j * 16384 + j * 128 + o];
        else        v = Ww[(size_t)j * 16384 + i * 128 + o]
                      + Ww[(size_t)i * 16384 + j * 128 + o];
    }                                   // else zero padding row
    const int kb = t >> 5, ks = (t >> 3) & 3, kk = t & 7;
    const int hb = kk >> 2, tg = kk & 3;
    const int wn = o >> 5, nt = (o >> 3) & 3, gid = o & 7;
    const size_t dst = (size_t)kb * 4096 + ks * 1024 + wn * 256 + hb * 128
                     + (gid * 4 + tg) * 4 + nt;
    g_Ws[dst] = tf32_rna(v);
}

// ---------------- main kernel ----------------
// SMEM: X[64][132]f @0 (33792) | cidx u32[1104] @33792 (4416)
//       A frag-major [2][4mb][4ks][32lane][4]f @38208 (2x8192)
//       B frag-major [3][16KB]                 @54592 (3x16384)
static constexpr int X_OFF = 0;
static constexpr int CIDX_OFF = 33792;
static constexpr int A_OFF = 38208;
static constexpr int B_OFF = 54592;
static constexpr int SMEM_TOTAL = 103744;

__global__ void __launch_bounds__(256) k_main(const float* __restrict__ x,
                                              const float* __restrict__ bb,
                                              float* __restrict__ y) {
    extern __shared__ char smem[];
    float*    sX = (float*)(smem + X_OFF);
    uint32_t* sC = (uint32_t*)(smem + CIDX_OFF);

    const int tid = threadIdx.x;
    const int m0 = blockIdx.x * 64;
    const int lane = tid & 31, wid = tid >> 5;
    const int wm = wid & 1, wn = wid >> 1;       // 8 warps: tile 32(M) x 32(N)
    const int gid = lane >> 2, tg = lane & 3;

    // Load X tile (64 x 128, smem row stride 132 floats)
    {
        const int r = tid >> 2, q = tid & 3;
        const float4* src = (const float4*)(x + (size_t)(m0 + r) * 128) + q * 8;
        float4* dst = (float4*)(sX + r * 132) + q * 8;
#pragma unroll
        for (int c = 0; c < 8; c++) dst[c] = src[c];
    }
#pragma unroll
    for (int k = 0; k < 5; k++) {
        int e = tid + k * 256;
        if (e < NCHUNK) sC[e] = g_cidx[e];
    }

    // B staging: 16KB contiguous copy per kb (already fragment-ordered)
    auto cpasyncB = [&](int kb, int st) {
        const float* srcbase = g_Ws + (size_t)kb * 4096;
        const uint32_t dstbase = smem_u32(smem + B_OFF + st * 16384);
#pragma unroll
        for (int c = 0; c < 4; c++) {
            const int chunk = tid + c * 256;          // 1024 chunks of 16B
            asm volatile("cp.async.cg.shared.global [%0], [%1], 16;"
                         :: "r"(dstbase + (uint32_t)(chunk * 16)),
                            "l"(srcbase + chunk * 4));
        }
        asm volatile("cp.async.commit_group;");
    };

    // A builder: 2 frag quads per thread (512 quads = full 64x32 A tile)
    auto buildA = [&](int kb, int st) {
        float4* base = (float4*)(smem + A_OFF + st * 8192);
#pragma unroll
        for (int qq = 0; qq < 2; qq++) {
            const int Q = tid + qq * 256;
            const int mb = Q >> 7, ks = (Q >> 5) & 3, l = Q & 31;
            const int r = l >> 2, c = l & 3;
            const int mr0 = mb * 16 + r, mr1 = mr0 + 8;
            const uint32_t e = sC[kb * 4 + ks];
            const int j = e >> 16;
            const bool bias = (j == 255);
            int i0 = (int)((e >> 8) & 255) + c;
            int i1 = i0 + 4;
            i0 = i0 < 127 ? i0 : 127;                 // padding rows have zero weight
            i1 = i1 < 127 ? i1 : 127;
            const float xj0 = bias ? 1.0f : sX[mr0 * 132 + j];
            const float xj1 = bias ? 1.0f : sX[mr1 * 132 + j];
            float4 w;
            w.x = tf32_rna(xj0 * sX[mr0 * 132 + i0]);
            w.y = tf32_rna(xj1 * sX[mr1 * 132 + i0]);
            w.z = tf32_rna(xj0 * sX[mr0 * 132 + i1]);
            w.w = tf32_rna(xj1 * sX[mr1 * 132 + i1]);
            base[Q] = w;
        }
    };
    __syncthreads();

    // Prologue: B(0), B(1) in flight; A(0) built
    cpasyncB(0, 0);
    cpasyncB(1, 1);
    buildA(0, 0);
    asm volatile("cp.async.wait_group 1;");       // B(0) resident, B(1) flying
    __syncthreads();

    float acc[2][4][4] = {};
    int curB = 0, nxtB = 2;

    for (int kb = 0; kb < NKB; kb++) {
        const int curA = kb & 1;
        if (kb + 2 < NKB) cpasyncB(kb + 2, nxtB);
        else asm volatile("cp.async.commit_group;");    // keep group count uniform
        if (kb + 1 < NKB) buildA(kb + 1, curA ^ 1);

        const float4* Af = (const float4*)(smem + A_OFF + curA * 8192);
        const char*   Bs = smem + B_OFF + curB * 16384;
#pragma unroll
        for (int ks = 0; ks < 4; ks++) {
            float4 a[2];
            a[0] = Af[((wm * 2 + 0) * 4 + ks) * 32 + lane];
            a[1] = Af[((wm * 2 + 1) * 4 + ks) * 32 + lane];
            const float4 bv0 = *(const float4*)(Bs + ks * 4096 + wn * 1024 + lane * 16);
            const float4 bv1 = *(const float4*)(Bs + ks * 4096 + wn * 1024 + 512 + lane * 16);
            const float b0a[4] = {bv0.x, bv0.y, bv0.z, bv0.w};
            const float b1a[4] = {bv1.x, bv1.y, bv1.z, bv1.w};
#pragma unroll
            for (int mt = 0; mt < 2; mt++) {
                const uint32_t a0 = __float_as_uint(((const float*)&a[mt])[0]);
                const uint32_t a1 = __float_as_uint(((const float*)&a[mt])[1]);
                const uint32_t a2 = __float_as_uint(((const float*)&a[mt])[2]);
                const uint32_t a3 = __float_as_uint(((const float*)&a[mt])[3]);
#pragma unroll
                for (int nt = 0; nt < 4; nt++) {
                    asm volatile(
                        "mma.sync.aligned.m16n8k8.row.col.f32.tf32.tf32.f32 "
                        "{%0,%1,%2,%3}, {%4,%5,%6,%7}, {%8,%9}, {%0,%1,%2,%3};"
                        : "+f"(acc[mt][nt][0]), "+f"(acc[mt][nt][1]),
                          "+f"(acc[mt][nt][2]), "+f"(acc[mt][nt][3])
                        : "r"(a0), "r"(a1), "r"(a2), "r"(a3),
                          "r"(__float_as_uint(b0a[nt])), "r"(__float_as_uint(b1a[nt])));
                }
            }
        }
        asm volatile("cp.async.wait_group 1;");   // B(kb+1) resident; B(kb+2) may fly
        __syncthreads();
        curB = (curB == 2) ? 0 : curB + 1;
        nxtB = (nxtB == 2) ? 0 : nxtB + 1;
    }

    // Epilogue: add bb, store
#pragma unroll
    for (int mt = 0; mt < 2; mt++) {
        const int mrow = m0 + wm * 32 + mt * 16 + gid;
#pragma unroll
        for (int nt = 0; nt < 4; nt++) {
            const int n = wn * 32 + nt * 8 + tg * 2;
            const float c0 = __ldg(bb + n), c1 = __ldg(bb + n + 1);
            float* p0 = y + (size_t)mrow * 128 + n;
            float* p1 = p0 + 8 * 128;
            ((float2*)p0)[0] = make_float2(acc[mt][nt][0] + c0, acc[mt][nt][1] + c1);
            ((float2*)p1)[0] = make_float2(acc[mt][nt][2] + c0, acc[mt][nt][3] + c1);
        }
    }
}

extern "C" void kernel_launch(void* const* d_in, const int* in_sizes, int n_in,
                              void* d_out, int out_size) {
    const float* x  = (const float*)d_in[0];
    const float* Wb = (const float*)d_in[1];
    const float* bb = (const float*)d_in[2];
    const float* Ww = (const float*)d_in[3];
    const float* bw = (const float*)d_in[4];
    float* y = (float*)d_out;

    static bool attr_set = false;
    if (!attr_set) {
        cudaFuncSetAttribute(k_main, cudaFuncAttributeMaxDynamicSharedMemorySize, SMEM_TOTAL);
        attr_set = true;
    }

    k_prepW<<<NK, 128>>>(Ww, Wb, bw);
    k_main<<<128, 256, SMEM_TOTAL>>>(x, bb, y);
}